// round 6
// baseline (speedup 1.0000x reference)
#include <cuda_runtime.h>

#define KNEI 8
#define EHID 16
// 256 threads per block = 64 agents per block, 4 threads per agent.

__device__ __forceinline__ float ex2f(float x) {
    float r; asm("ex2.approx.f32 %0, %1;" : "=f"(r) : "f"(x)); return r;
}

struct Net { float w[EHID]; float c[EHID]; float bias; int nnz; };
__device__ Net  g_nets[4];   // 0=rep, 1=att, 2=bor, 3=del
__device__ float g_scal[8];  // inv_p0, p1, ang^2, border[0], border[3]

// ---------------------------------------------------------------------------
// Fold each mono net  y = b2 + sum_i w2_i * exp(-(w1_i x + b1_i))
// into               y = bias + sum_{w1_i != 0} c_i * exp2(w'_i * x)
// ---------------------------------------------------------------------------
__global__ void sfm_preprocess(
    const float* __restrict__ rep_w1, const float* __restrict__ rep_b1,
    const float* __restrict__ rep_w2, const float* __restrict__ rep_b2,
    const float* __restrict__ att_w1, const float* __restrict__ att_b1,
    const float* __restrict__ att_w2, const float* __restrict__ att_b2,
    const float* __restrict__ bor_w1, const float* __restrict__ bor_b1,
    const float* __restrict__ bor_w2, const float* __restrict__ bor_b2,
    const float* __restrict__ del_w1, const float* __restrict__ del_b1,
    const float* __restrict__ del_w2, const float* __restrict__ del_b2,
    const float* __restrict__ p_dest, const float* __restrict__ angle,
    const float* __restrict__ border)
{
    int t = threadIdx.x;
    if (t < 4) {
        const float* w1 = (t==0)?rep_w1:(t==1)?att_w1:(t==2)?bor_w1:del_w1;
        const float* b1 = (t==0)?rep_b1:(t==1)?att_b1:(t==2)?bor_b1:del_b1;
        const float* w2 = (t==0)?rep_w2:(t==1)?att_w2:(t==2)?bor_w2:del_w2;
        const float* b2 = (t==0)?rep_b2:(t==1)?att_b2:(t==2)?bor_b2:del_b2;
        const float LOG2E = 1.4426950408889634f;
        float bias = b2[0];
        int m = 0;
        for (int i = 0; i < EHID; i++) {
            float ci = w2[i] * expf(-b1[i]);
            float wi = w1[i];
            if (wi != 0.0f) {
                g_nets[t].w[m] = -wi * LOG2E;
                g_nets[t].c[m] = ci;
                m++;
            } else {
                bias += ci;
            }
        }
        for (int i = m; i < EHID; i++) { g_nets[t].w[i] = 0.0f; g_nets[t].c[i] = 0.0f; }
        g_nets[t].bias = bias;
        g_nets[t].nnz  = m;
    } else if (t == 4) {
        g_scal[0] = 1.0f / p_dest[0];
        g_scal[1] = p_dest[1];
        float a = angle[0];
        g_scal[2] = a * a;
        g_scal[3] = border[0];
        g_scal[4] = border[3];
    }
}

template <int NB>
__device__ __forceinline__ void mono_batch(const float2* __restrict__ terms,
                                           int nn, float bias,
                                           const float* __restrict__ x,
                                           float* __restrict__ y)
{
#pragma unroll
    for (int k = 0; k < NB; k++) y[k] = bias;
    for (int t = 0; t < nn; t++) {
        float2 wc = terms[t];
#pragma unroll
        for (int k = 0; k < NB; k++)
            y[k] = fmaf(wc.y, ex2f(wc.x * x[k]), y[k]);
    }
}

__device__ __forceinline__ float mono1(const float2* __restrict__ terms,
                                       int nn, float bias, float x)
{
    float y = bias;
    for (int t = 0; t < nn; t++) {
        float2 wc = terms[t];
        y = fmaf(wc.y, ex2f(wc.x * x), y);
    }
    return y;
}

__global__ void __launch_bounds__(256, 4)
sfm_main(const float* __restrict__ ego, const float* __restrict__ nei,
         const float* __restrict__ rec, float* __restrict__ out, int N)
{
    __shared__ float2 sT[4][EHID];
    __shared__ float  sB[4];
    __shared__ int    sN[4];
    __shared__ float  sS[8];

    int t = threadIdx.x;
    if (t < 64) {
        int q = t >> 4, i = t & 15;
        sT[q][i] = make_float2(g_nets[q].w[i], g_nets[q].c[i]);
    } else if (t < 68) {
        sB[t - 64] = g_nets[t - 64].bias;
        sN[t - 64] = g_nets[t - 64].nnz;
    } else if (t < 73) {
        sS[t - 68] = g_scal[t - 68];
    }
    __syncthreads();

    const unsigned FULL = 0xffffffffu;
    int qid = t >> 2;          // agent index within block
    int h   = t & 3;           // lane-in-quad: owns neighbor/buffer slots 2h, 2h+1
    int n   = blockIdx.x * 64 + qid;
    if (n >= N) return;        // whole quads (and warps) exit together

    // ============ front-batched loads ============
    // own 2 nei rows (first 16B + vny scalar in same 32B sector)
    const float* nb = nei + (size_t)n * (KNEI * 16);
    float4 a4[2];
    float  vny[2];
#pragma unroll
    for (int j = 0; j < 2; j++)
        a4[j] = *reinterpret_cast<const float4*>(nb + (size_t)(2 * h + j) * 16);
#pragma unroll
    for (int j = 0; j < 2; j++)
        vny[j] = __ldg(nb + (size_t)(2 * h + j) * 16 + 4);

    // full ego row (all 4 lanes load the same addresses: L1 broadcast)
    const float4* e4 = reinterpret_cast<const float4*>(ego) + (size_t)n * 4;
    float4 e0 = e4[0], e1 = e4[1], e2 = e4[2], e3 = e4[3];

    // own quarter of rec: float4 h = (bid[2h], ct[2h], bid[2h+1], ct[2h+1])
    const float4* r4 = reinterpret_cast<const float4*>(rec) + (size_t)n * 4;
    float4 rr = r4[h];

    // ============ unpack ego ============
    float px = e0.y, py = e0.z;
    float vx = e0.w, vy = e1.x;
    float ids[8] = { e1.w, e2.x, e2.y, e2.z, e2.w, e3.x, e3.y, e3.z };

    // ============ gather full (unordered) neighbor-id set: 6 shuffles ======
    float n0a = a4[0].x, n0b = a4[1].x;
    float n1a = __shfl_xor_sync(FULL, n0a, 1);
    float n1b = __shfl_xor_sync(FULL, n0b, 1);
    float n2a = __shfl_xor_sync(FULL, n0a, 2);
    float n2b = __shfl_xor_sync(FULL, n0b, 2);
    float n3a = __shfl_xor_sync(FULL, n1a, 2);
    float n3b = __shfl_xor_sync(FULL, n1b, 2);

    // ============ buffer logic on own 2 slots ============
    float bidl[2] = { rr.x, rr.z };
    float bctl[2] = { rr.y, rr.w };
    unsigned mown = 0;
    float ct2l[2];
#pragma unroll
    for (int i = 0; i < 2; i++) {
        float b = bidl[i];
        bool f = (b == n0a) | (b == n0b) | (b == n1a) | (b == n1b) |
                 (b == n2a) | (b == n2b) | (b == n3a) | (b == n3b);
        mown |= (f ? 1u : 0u) << (2 * h + i);
        ct2l[i] = bctl[i] + (f ? 1.0f : 0.0f);
    }
    unsigned m4 = mown | __shfl_xor_sync(FULL, mown, 1);
    unsigned m8 = m4   | __shfl_xor_sync(FULL, m4,   2);

    // count for own global slots gi = 2h + i:
    // k* = slot index of the gi-th set bit of m8 (slot order = buffer order),
    // then fetch ct2 of slot k* from its owning lane via shfl.idx.
    int laneid = t & 31;
    float countl[2];
#pragma unroll
    for (int i = 0; i < 2; i++) {
        int gi = 2 * h + i;
        int kstar = 8;
#pragma unroll
        for (int k = 0; k < 8; k++) {
            bool bset = (m8 >> k) & 1u;
            int  rank = __popc(m8 & ((1u << k) - 1u));
            kstar = (bset && rank == gi && kstar == 8) ? k : kstar;
        }
        int ks  = kstar & 7;
        int src = (laneid & ~3) | (ks >> 1);
        float ce = __shfl_sync(FULL, ct2l[0], src);
        float co = __shfl_sync(FULL, ct2l[1], src);
        countl[i] = (kstar > 7) ? 1.0f : ((ks & 1) ? co : ce);
    }

    // ============ geometry for own 2 neighbors ============
    bool  idxk[2];
    float rnv[2], bv[2], dxv[2], dyv[2];
#pragma unroll
    for (int j = 0; j < 2; j++) {
        float id = a4[j].x;
        bool m = false;
#pragma unroll
        for (int q = 0; q < 8; q++) m |= (id == ids[q]);
        bool ix = m && (id != 0.0f);
        idxk[j] = ix;

        float rx = a4[j].y - px, ry = a4[j].z - py;
        float s  = rx * rx + ry * ry;
        float ir = rsqrtf(s);
        float rn = s * ir;
        rnv[j] = rn;
        dxv[j] = rx * ir;
        dyv[j] = ry * ir;

        float vdx = a4[j].w * 0.02f, vdy = vny[j] * 0.02f;
        float tx = rx + vdx, ty = ry + vdy;
        float bb = rn + tx * tx + ty * ty - (vdx * vdx + vdy * vdy);
        bb = ix ? bb : 1.0f;
        bv[j] = __fsqrt_rn(fmaxf(bb, 1e-12f)) * 0.5f;
    }

    // ============ mono nets on own 2 ============
    float att2[2], rep2[2], del2[2];
    mono_batch<2>(sT[1], sN[1], sB[1], rnv, att2);
    mono_batch<2>(sT[0], sN[0], sB[0], bv,  rep2);

    bool same = (countl[0] == countl[1]);
    float c1 = __shfl_xor_sync(FULL, countl[0], 1);
    float c2 = __shfl_xor_sync(FULL, countl[0], 2);
    same = same && (countl[0] == c1) && (countl[0] == c2);
    if (__all_sync(FULL, same)) {
        float du = mono1(sT[3], sN[3], sB[3], countl[0]);
        del2[0] = du; del2[1] = du;
    } else {
        mono_batch<2>(sT[3], sN[3], sB[3], countl, del2);
    }

    float v2   = vx * vx + vy * vy;
    float ang2 = sS[2];

    // ============ neighbor forces (own 2), angle-clamped, quad-reduced =====
    float fnx = 0.0f, fny = 0.0f;
#pragma unroll
    for (int j = 0; j < 2; j++) {
        bool ix = idxk[j];
        float da  = del2[j] * att2[j];
        float fax = ix ? da * dxv[j] : 0.0f;
        float fay = ix ? da * dyv[j] : 0.0f;
        float frx = ix ? rep2[j] * dxv[j] : 0.0f;
        float fry = ix ? rep2[j] * dyv[j] : 0.0f;

        float num = vx * fax + vy * fay;
        float nn  = fax * fax + fay * fay;
        bool keep = num * num > ang2 * fmaxf(v2 * nn, 1e-16f);
        fnx += keep ? fax : 0.0f;
        fny += keep ? fay : 0.0f;

        num  = vx * frx + vy * fry;
        nn   = frx * frx + fry * fry;
        keep = num * num > ang2 * fmaxf(v2 * nn, 1e-16f);
        fnx += keep ? frx : 0.0f;
        fny += keep ? fry : 0.0f;
    }
    fnx += __shfl_xor_sync(FULL, fnx, 1);
    fnx += __shfl_xor_sync(FULL, fnx, 2);
    fny += __shfl_xor_sync(FULL, fny, 1);
    fny += __shfl_xor_sync(FULL, fny, 2);

    // ============ border force: lanes h=0,1 each handle one border term ====
    float bxc = e0.z;
    float fbyl = 0.0f;
    if (h < 2) {
        float rb = bxc - sS[3 + h];
        float bm = mono1(sT[2], sN[2], sB[2], fabsf(rb));
        float fv = bm * copysignf(1.0f, rb);
        float num = vy * fv, nn = fv * fv;
        if (num * num > ang2 * fmaxf(v2 * nn, 1e-16f)) fbyl = fv;
    }
    float fby = fbyl + __shfl_xor_sync(FULL, fbyl, 1);
    fby += __shfl_xor_sync(FULL, fby, 2);

    // ============ destination force (cheap: computed by all lanes) =========
    float speed = __fsqrt_rn(v2);
    float ip0 = sS[0], p1 = sS[1];
    float fdx = (p1 * speed - vx) * ip0;
    float fdy = (-vy) * ip0;
    {
        float num = vx * fdx + vy * fdy;
        float nn  = fdx * fdx + fdy * fdy;
        bool keep = num * num > ang2 * fmaxf(v2 * nn, 1e-16f);
        fdx = keep ? fdx : 0.0f;
        fdy = keep ? fdy : 0.0f;
    }

    // ============ output: (N, 3, 2); quad splits the 3 float2 stores =======
    float2* o = reinterpret_cast<float2*>(out) + (size_t)n * 3;
    if (h == 0)      o[0] = make_float2(fdx, fdy);
    else if (h == 1) o[1] = make_float2(fnx, fny);
    else if (h == 2) o[2] = make_float2(0.0f, fby);
}

extern "C" void kernel_launch(void* const* d_in, const int* in_sizes, int n_in,
                              void* d_out, int out_size)
{
    const float* ego    = (const float*)d_in[0];
    const float* nei    = (const float*)d_in[1];
    const float* border = (const float*)d_in[2];
    const float* rec    = (const float*)d_in[3];
    const float* p_dest = (const float*)d_in[4];
    const float* angle  = (const float*)d_in[5];

    sfm_preprocess<<<1, 32>>>(
        (const float*)d_in[6],  (const float*)d_in[7],  (const float*)d_in[8],  (const float*)d_in[9],
        (const float*)d_in[10], (const float*)d_in[11], (const float*)d_in[12], (const float*)d_in[13],
        (const float*)d_in[14], (const float*)d_in[15], (const float*)d_in[16], (const float*)d_in[17],
        (const float*)d_in[18], (const float*)d_in[19], (const float*)d_in[20], (const float*)d_in[21],
        p_dest, angle, border);

    int N = in_sizes[0] / 16;
    int blocks = (N + 63) / 64;   // 64 agents per block, 256 threads
    sfm_main<<<blocks, 256>>>(ego, nei, rec, (float*)d_out, N);
}

// round 7
// speedup vs baseline: 1.3547x; 1.3547x over previous
#include <cuda_runtime.h>

#define KNEI 8
#define EHID 16
// 256 threads per block = 128 agents per block, 2 threads per agent.

__device__ __forceinline__ float ex2f(float x) {
    float r; asm("ex2.approx.f32 %0, %1;" : "=f"(r) : "f"(x)); return r;
}

struct Net { float w[EHID]; float c[EHID]; float bias; int nnz; };
__device__ Net  g_nets[4];   // 0=rep, 1=att, 2=bor, 3=del
__device__ float g_scal[8];  // inv_p0, p1, ang^2, border[0], border[3]

// ---------------------------------------------------------------------------
// Fold each mono net  y = b2 + sum_i w2_i * exp(-(w1_i x + b1_i))
// into               y = bias + sum_{w1_i != 0} c_i * exp2(w'_i * x)
// ---------------------------------------------------------------------------
__global__ void sfm_preprocess(
    const float* __restrict__ rep_w1, const float* __restrict__ rep_b1,
    const float* __restrict__ rep_w2, const float* __restrict__ rep_b2,
    const float* __restrict__ att_w1, const float* __restrict__ att_b1,
    const float* __restrict__ att_w2, const float* __restrict__ att_b2,
    const float* __restrict__ bor_w1, const float* __restrict__ bor_b1,
    const float* __restrict__ bor_w2, const float* __restrict__ bor_b2,
    const float* __restrict__ del_w1, const float* __restrict__ del_b1,
    const float* __restrict__ del_w2, const float* __restrict__ del_b2,
    const float* __restrict__ p_dest, const float* __restrict__ angle,
    const float* __restrict__ border)
{
    int t = threadIdx.x;
    if (t < 4) {
        const float* w1 = (t==0)?rep_w1:(t==1)?att_w1:(t==2)?bor_w1:del_w1;
        const float* b1 = (t==0)?rep_b1:(t==1)?att_b1:(t==2)?bor_b1:del_b1;
        const float* w2 = (t==0)?rep_w2:(t==1)?att_w2:(t==2)?bor_w2:del_w2;
        const float* b2 = (t==0)?rep_b2:(t==1)?att_b2:(t==2)?bor_b2:del_b2;
        const float LOG2E = 1.4426950408889634f;
        float bias = b2[0];
        int m = 0;
        for (int i = 0; i < EHID; i++) {
            float ci = w2[i] * expf(-b1[i]);
            float wi = w1[i];
            if (wi != 0.0f) {
                g_nets[t].w[m] = -wi * LOG2E;
                g_nets[t].c[m] = ci;
                m++;
            } else {
                bias += ci;
            }
        }
        for (int i = m; i < EHID; i++) { g_nets[t].w[i] = 0.0f; g_nets[t].c[i] = 0.0f; }
        g_nets[t].bias = bias;
        g_nets[t].nnz  = m;
    } else if (t == 4) {
        g_scal[0] = 1.0f / p_dest[0];
        g_scal[1] = p_dest[1];
        float a = angle[0];
        g_scal[2] = a * a;
        g_scal[3] = border[0];
        g_scal[4] = border[3];
    }
}

template <int NB>
__device__ __forceinline__ void mono_batch(const float2* __restrict__ terms,
                                           int nn, float bias,
                                           const float* __restrict__ x,
                                           float* __restrict__ y)
{
#pragma unroll
    for (int k = 0; k < NB; k++) y[k] = bias;
    for (int t = 0; t < nn; t++) {
        float2 wc = terms[t];
#pragma unroll
        for (int k = 0; k < NB; k++)
            y[k] = fmaf(wc.y, ex2f(wc.x * x[k]), y[k]);
    }
}

__device__ __forceinline__ float mono1(const float2* __restrict__ terms,
                                       int nn, float bias, float x)
{
    float y = bias;
    for (int t = 0; t < nn; t++) {
        float2 wc = terms[t];
        y = fmaf(wc.y, ex2f(wc.x * x), y);
    }
    return y;
}

__global__ void __launch_bounds__(256, 5)
sfm_main(const float* __restrict__ ego, const float* __restrict__ nei,
         const float* __restrict__ rec, float* __restrict__ out, int N)
{
    __shared__ float2 sT[4][EHID];
    __shared__ float  sB[4];
    __shared__ int    sN[4];
    __shared__ float  sS[8];

    int t = threadIdx.x;
    if (t < 64) {
        int q = t >> 4, i = t & 15;
        sT[q][i] = make_float2(g_nets[q].w[i], g_nets[q].c[i]);
    } else if (t < 68) {
        sB[t - 64] = g_nets[t - 64].bias;
        sN[t - 64] = g_nets[t - 64].nnz;
    } else if (t < 73) {
        sS[t - 68] = g_scal[t - 68];
    }
    __syncthreads();

    int pid = t >> 1;          // pair (agent) index within block
    int h   = t & 1;           // half: this thread owns neighbor/buffer slots 4h..4h+3
    int n   = blockIdx.x * 128 + pid;
    if (n >= N) return;        // whole pairs exit together

    unsigned amask = __activemask();

    // ============ front-batched loads: own 4 nei rows + full ego + own rec half
    const float* nb = nei + (size_t)n * (KNEI * 16);
    float4 a4[4];
    float  vny[4];
#pragma unroll
    for (int j = 0; j < 4; j++)
        a4[j] = *reinterpret_cast<const float4*>(nb + (size_t)(4 * h + j) * 16);
#pragma unroll
    for (int j = 0; j < 4; j++)
        vny[j] = __ldg(nb + (size_t)(4 * h + j) * 16 + 4);   // same sector as a4[j]

    const float4* e4 = reinterpret_cast<const float4*>(ego) + (size_t)n * 4;
    float4 e0 = e4[0], e1 = e4[1], e2 = e4[2], e3 = e4[3];

    const float4* r4 = reinterpret_cast<const float4*>(rec) + (size_t)n * 4;
    float4 rr0 = r4[2 * h], rr1 = r4[2 * h + 1];

    // ============ unpack ego ============
    float px = e0.y, py = e0.z;
    float vx = e0.w, vy = e1.x;
    float ids[8] = { e1.w, e2.x, e2.y, e2.z, e2.w, e3.x, e3.y, e3.z };

    // ============ exchange neighbor ids -> full global-order nid8 ============
    float nidl[4] = { a4[0].x, a4[1].x, a4[2].x, a4[3].x };
    float nid8[8];
#pragma unroll
    for (int j = 0; j < 4; j++) {
        float o = __shfl_xor_sync(amask, nidl[j], 1);
        nid8[j]     = h ? o       : nidl[j];   // global slots 0..3
        nid8[4 + j] = h ? nidl[j] : o;         // global slots 4..7
    }

    // ============ buffer logic on own 4 slots ============
    float bidl[4] = { rr0.x, rr0.z, rr1.x, rr1.z };
    float bctl[4] = { rr0.y, rr0.w, rr1.y, rr1.w };
    unsigned mown = 0;
    float ct2l[4];
#pragma unroll
    for (int i = 0; i < 4; i++) {
        bool f = false;
#pragma unroll
        for (int j = 0; j < 8; j++) f |= (bidl[i] == nid8[j]);
        mown |= (f ? 1u : 0u) << (4 * h + i);
        ct2l[i] = bctl[i] + (f ? 1.0f : 0.0f);
    }
    unsigned m8 = mown | __shfl_xor_sync(amask, mown, 1);

    // exchange ct2 -> full buffer-order ct8
    float ct8[8];
#pragma unroll
    for (int i = 0; i < 4; i++) {
        float o = __shfl_xor_sync(amask, ct2l[i], 1);
        ct8[i]     = h ? o       : ct2l[i];
        ct8[4 + i] = h ? ct2l[i] : o;
    }

    // count for own global slots gi = 4h+i:
    // k* = position of the (gi+1)-th set bit of m8 (buffer order); select ct8[k*]
    float countl[4];
#pragma unroll
    for (int i = 0; i < 4; i++) {
        int gi = 4 * h + i;
        unsigned k = __fns(m8, 0, gi + 1);     // 0xFFFFFFFF if fewer set bits
        bool valid = (k < 8u);
        unsigned kk = k & 7u;
        float s0 = (kk & 1u) ? ct8[1] : ct8[0];
        float s1 = (kk & 1u) ? ct8[3] : ct8[2];
        float s2 = (kk & 1u) ? ct8[5] : ct8[4];
        float s3 = (kk & 1u) ? ct8[7] : ct8[6];
        float u0 = (kk & 2u) ? s1 : s0;
        float u1 = (kk & 2u) ? s3 : s2;
        float cv = (kk & 4u) ? u1 : u0;
        countl[i] = valid ? cv : 1.0f;
    }

    // ============ geometry for own 4 neighbors ============
    bool  idxk[4];
    float rnv[4], bv[4], dxv[4], dyv[4];
#pragma unroll
    for (int j = 0; j < 4; j++) {
        float id = a4[j].x;
        bool m = false;
#pragma unroll
        for (int q = 0; q < 8; q++) m |= (id == ids[q]);
        bool ix = m && (id != 0.0f);
        idxk[j] = ix;

        float rx = a4[j].y - px, ry = a4[j].z - py;
        float s  = rx * rx + ry * ry;
        float ir = rsqrtf(s);
        float rn = s * ir;
        rnv[j] = rn;
        dxv[j] = rx * ir;
        dyv[j] = ry * ir;

        float vdx = a4[j].w * 0.02f, vdy = vny[j] * 0.02f;
        float tx = rx + vdx, ty = ry + vdy;
        float bb = rn + tx * tx + ty * ty - (vdx * vdx + vdy * vdy);
        bb = ix ? bb : 1.0f;
        bv[j] = __fsqrt_rn(fmaxf(bb, 1e-12f)) * 0.5f;
    }

    // ============ mono nets on own 4 ============
    float att4[4], rep4[4], del4[4];
    mono_batch<4>(sT[1], sN[1], sB[1], rnv, att4);
    mono_batch<4>(sT[0], sN[0], sB[0], bv,  rep4);

    bool same = (countl[0] == countl[1]) & (countl[0] == countl[2]) &
                (countl[0] == countl[3]);
    float oc0 = __shfl_xor_sync(amask, countl[0], 1);
    same = same && (countl[0] == oc0);
    if (__all_sync(amask, same)) {
        float du = mono1(sT[3], sN[3], sB[3], countl[0]);
#pragma unroll
        for (int j = 0; j < 4; j++) del4[j] = du;
    } else {
        mono_batch<4>(sT[3], sN[3], sB[3], countl, del4);
    }

    float v2   = vx * vx + vy * vy;
    float ang2 = sS[2];

    // ============ neighbor forces (own 4), angle-clamped, then pair-reduce ==
    float fnx = 0.0f, fny = 0.0f;
#pragma unroll
    for (int j = 0; j < 4; j++) {
        bool ix = idxk[j];
        float da  = del4[j] * att4[j];
        float fax = ix ? da * dxv[j] : 0.0f;
        float fay = ix ? da * dyv[j] : 0.0f;
        float frx = ix ? rep4[j] * dxv[j] : 0.0f;
        float fry = ix ? rep4[j] * dyv[j] : 0.0f;

        float num = vx * fax + vy * fay;
        float nn  = fax * fax + fay * fay;
        bool keep = num * num > ang2 * fmaxf(v2 * nn, 1e-16f);
        fnx += keep ? fax : 0.0f;
        fny += keep ? fay : 0.0f;

        num  = vx * frx + vy * fry;
        nn   = frx * frx + fry * fry;
        keep = num * num > ang2 * fmaxf(v2 * nn, 1e-16f);
        fnx += keep ? frx : 0.0f;
        fny += keep ? fry : 0.0f;
    }
    fnx += __shfl_xor_sync(amask, fnx, 1);
    fny += __shfl_xor_sync(amask, fny, 1);

    // ============ border force: this thread handles border term h ==========
    float bxc = e0.z;
    float rb  = bxc - sS[3 + h];
    float bm  = mono1(sT[2], sN[2], sB[2], fabsf(rb));
    float fv  = bm * copysignf(1.0f, rb);
    float fbyl = 0.0f;
    {
        float num = vy * fv, nn = fv * fv;
        if (num * num > ang2 * fmaxf(v2 * nn, 1e-16f)) fbyl = fv;
    }
    float fby = fbyl + __shfl_xor_sync(amask, fbyl, 1);

    // ============ destination force ============
    float speed = __fsqrt_rn(v2);
    float ip0 = sS[0], p1 = sS[1];
    float fdx = (p1 * speed - vx) * ip0;
    float fdy = (-vy) * ip0;
    {
        float num = vx * fdx + vy * fdy;
        float nn  = fdx * fdx + fdy * fdy;
        bool keep = num * num > ang2 * fmaxf(v2 * nn, 1e-16f);
        fdx = keep ? fdx : 0.0f;
        fdy = keep ? fdy : 0.0f;
    }

    // ============ output: (N, 3, 2); pair splits the 3 float2 stores =======
    float2* o = reinterpret_cast<float2*>(out) + (size_t)n * 3;
    if (h == 0) {
        o[0] = make_float2(fdx, fdy);
        o[1] = make_float2(fnx, fny);
    } else {
        o[2] = make_float2(0.0f, fby);
    }
}

extern "C" void kernel_launch(void* const* d_in, const int* in_sizes, int n_in,
                              void* d_out, int out_size)
{
    const float* ego    = (const float*)d_in[0];
    const float* nei    = (const float*)d_in[1];
    const float* border = (const float*)d_in[2];
    const float* rec    = (const float*)d_in[3];
    const float* p_dest = (const float*)d_in[4];
    const float* angle  = (const float*)d_in[5];

    sfm_preprocess<<<1, 32>>>(
        (const float*)d_in[6],  (const float*)d_in[7],  (const float*)d_in[8],  (const float*)d_in[9],
        (const float*)d_in[10], (const float*)d_in[11], (const float*)d_in[12], (const float*)d_in[13],
        (const float*)d_in[14], (const float*)d_in[15], (const float*)d_in[16], (const float*)d_in[17],
        (const float*)d_in[18], (const float*)d_in[19], (const float*)d_in[20], (const float*)d_in[21],
        p_dest, angle, border);

    int N = in_sizes[0] / 16;
    int blocks = (N + 127) / 128;   // 128 agents per block, 256 threads
    sfm_main<<<blocks, 256>>>(ego, nei, rec, (float*)d_out, N);
}

// round 8
// speedup vs baseline: 1.6176x; 1.1941x over previous
#include <cuda_runtime.h>

#define KNEI 8
#define EHID 16
// 256 threads per block = 128 agents per block, 2 threads per agent.

__device__ __forceinline__ float ex2f(float x) {
    float r; asm("ex2.approx.f32 %0, %1;" : "=f"(r) : "f"(x)); return r;
}

struct Net { float w[EHID]; float c[EHID]; float bias; int nnz; };
__device__ Net  g_nets[4];   // 0=rep, 1=att, 2=bor, 3=del
__device__ float g_scal[8];  // inv_p0, p1, ang^2, border[0], border[3]

// ---------------------------------------------------------------------------
// Fold each mono net  y = b2 + sum_i w2_i * exp(-(w1_i x + b1_i))
// into               y = bias + sum_{w1_i != 0} c_i * exp2(w'_i * x)
// ---------------------------------------------------------------------------
__global__ void sfm_preprocess(
    const float* __restrict__ rep_w1, const float* __restrict__ rep_b1,
    const float* __restrict__ rep_w2, const float* __restrict__ rep_b2,
    const float* __restrict__ att_w1, const float* __restrict__ att_b1,
    const float* __restrict__ att_w2, const float* __restrict__ att_b2,
    const float* __restrict__ bor_w1, const float* __restrict__ bor_b1,
    const float* __restrict__ bor_w2, const float* __restrict__ bor_b2,
    const float* __restrict__ del_w1, const float* __restrict__ del_b1,
    const float* __restrict__ del_w2, const float* __restrict__ del_b2,
    const float* __restrict__ p_dest, const float* __restrict__ angle,
    const float* __restrict__ border)
{
    int t = threadIdx.x;
    if (t < 4) {
        const float* w1 = (t==0)?rep_w1:(t==1)?att_w1:(t==2)?bor_w1:del_w1;
        const float* b1 = (t==0)?rep_b1:(t==1)?att_b1:(t==2)?bor_b1:del_b1;
        const float* w2 = (t==0)?rep_w2:(t==1)?att_w2:(t==2)?bor_w2:del_w2;
        const float* b2 = (t==0)?rep_b2:(t==1)?att_b2:(t==2)?bor_b2:del_b2;
        const float LOG2E = 1.4426950408889634f;
        float bias = b2[0];
        int m = 0;
        for (int i = 0; i < EHID; i++) {
            float ci = w2[i] * expf(-b1[i]);
            float wi = w1[i];
            if (wi != 0.0f) {
                g_nets[t].w[m] = -wi * LOG2E;
                g_nets[t].c[m] = ci;
                m++;
            } else {
                bias += ci;
            }
        }
        for (int i = m; i < EHID; i++) { g_nets[t].w[i] = 0.0f; g_nets[t].c[i] = 0.0f; }
        g_nets[t].bias = bias;
        g_nets[t].nnz  = m;
    } else if (t == 4) {
        g_scal[0] = 1.0f / p_dest[0];
        g_scal[1] = p_dest[1];
        float a = angle[0];
        g_scal[2] = a * a;
        g_scal[3] = border[0];
        g_scal[4] = border[3];
    }
}

template <int NB>
__device__ __forceinline__ void mono_batch(const float2* __restrict__ terms,
                                           int nn, float bias,
                                           const float* __restrict__ x,
                                           float* __restrict__ y)
{
#pragma unroll
    for (int k = 0; k < NB; k++) y[k] = bias;
    for (int t = 0; t < nn; t++) {
        float2 wc = terms[t];
#pragma unroll
        for (int k = 0; k < NB; k++)
            y[k] = fmaf(wc.y, ex2f(wc.x * x[k]), y[k]);
    }
}

__device__ __forceinline__ float mono1(const float2* __restrict__ terms,
                                       int nn, float bias, float x)
{
    float y = bias;
    for (int t = 0; t < nn; t++) {
        float2 wc = terms[t];
        y = fmaf(wc.y, ex2f(wc.x * x), y);
    }
    return y;
}

__global__ void __launch_bounds__(256, 4)
sfm_main(const float* __restrict__ ego, const float* __restrict__ nei,
         const float* __restrict__ rec, float* __restrict__ out, int N)
{
    __shared__ float2 sT[4][EHID];
    __shared__ float  sB[4];
    __shared__ int    sN[4];
    __shared__ float  sS[8];

    int t = threadIdx.x;
    if (t < 64) {
        int q = t >> 4, i = t & 15;
        sT[q][i] = make_float2(g_nets[q].w[i], g_nets[q].c[i]);
    } else if (t < 68) {
        sB[t - 64] = g_nets[t - 64].bias;
        sN[t - 64] = g_nets[t - 64].nnz;
    } else if (t < 73) {
        sS[t - 68] = g_scal[t - 68];
    }
    __syncthreads();

    int pid = t >> 1;          // pair (agent) index within block
    int h   = t & 1;           // half: this thread owns neighbor/buffer slots 4h..4h+3
    int n   = blockIdx.x * 128 + pid;
    if (n >= N) return;        // whole pairs exit together

    unsigned amask = __activemask();

    // ============ front-batched loads: own 4 nei rows + full ego + own rec half
    const float* nb = nei + (size_t)n * (KNEI * 16);
    float4 a4[4];
    float  vny[4];
#pragma unroll
    for (int j = 0; j < 4; j++)
        a4[j] = *reinterpret_cast<const float4*>(nb + (size_t)(4 * h + j) * 16);
#pragma unroll
    for (int j = 0; j < 4; j++)
        vny[j] = __ldg(nb + (size_t)(4 * h + j) * 16 + 4);   // same sector as a4[j]

    const float4* e4 = reinterpret_cast<const float4*>(ego) + (size_t)n * 4;
    float4 e0 = e4[0], e1 = e4[1], e2 = e4[2], e3 = e4[3];

    const float4* r4 = reinterpret_cast<const float4*>(rec) + (size_t)n * 4;
    float4 rr0 = r4[2 * h], rr1 = r4[2 * h + 1];

    // ============ unpack ego ============
    float px = e0.y, py = e0.z;
    float vx = e0.w, vy = e1.x;
    float ids[8] = { e1.w, e2.x, e2.y, e2.z, e2.w, e3.x, e3.y, e3.z };

    // ============ exchange neighbor ids -> full global-order nid8 ============
    float nidl[4] = { a4[0].x, a4[1].x, a4[2].x, a4[3].x };
    float nid8[8];
#pragma unroll
    for (int j = 0; j < 4; j++) {
        float o = __shfl_xor_sync(amask, nidl[j], 1);
        nid8[j]     = h ? o       : nidl[j];   // global slots 0..3
        nid8[4 + j] = h ? nidl[j] : o;         // global slots 4..7
    }

    // ============ buffer logic on own 4 slots ============
    float bidl[4] = { rr0.x, rr0.z, rr1.x, rr1.z };
    float bctl[4] = { rr0.y, rr0.w, rr1.y, rr1.w };
    unsigned mown = 0;
    float ct2l[4];
#pragma unroll
    for (int i = 0; i < 4; i++) {
        bool f = false;
#pragma unroll
        for (int j = 0; j < 8; j++) f |= (bidl[i] == nid8[j]);
        mown |= (f ? 1u : 0u) << (4 * h + i);
        ct2l[i] = bctl[i] + (f ? 1.0f : 0.0f);
    }
    unsigned m8 = mown | __shfl_xor_sync(amask, mown, 1);

    // exchange ct2 -> full buffer-order ct8
    float ct8[8];
#pragma unroll
    for (int i = 0; i < 4; i++) {
        float o = __shfl_xor_sync(amask, ct2l[i], 1);
        ct8[i]     = h ? o       : ct2l[i];
        ct8[4 + i] = h ? ct2l[i] : o;
    }

    // count for own global slots gi = 4h+i:
    // k* = position of the (gi+1)-th set bit of m8 (buffer order); select ct8[k*]
    float countl[4];
#pragma unroll
    for (int i = 0; i < 4; i++) {
        int gi = 4 * h + i;
        unsigned k = __fns(m8, 0, gi + 1);     // 0xFFFFFFFF if fewer set bits
        bool valid = (k < 8u);
        unsigned kk = k & 7u;
        float s0 = (kk & 1u) ? ct8[1] : ct8[0];
        float s1 = (kk & 1u) ? ct8[3] : ct8[2];
        float s2 = (kk & 1u) ? ct8[5] : ct8[4];
        float s3 = (kk & 1u) ? ct8[7] : ct8[6];
        float u0 = (kk & 2u) ? s1 : s0;
        float u1 = (kk & 2u) ? s3 : s2;
        float cv = (kk & 4u) ? u1 : u0;
        countl[i] = valid ? cv : 1.0f;
    }

    // ============ geometry for own 4 neighbors ============
    bool  idxk[4];
    float rnv[4], bv[4], dxv[4], dyv[4];
#pragma unroll
    for (int j = 0; j < 4; j++) {
        float id = a4[j].x;
        bool m = false;
#pragma unroll
        for (int q = 0; q < 8; q++) m |= (id == ids[q]);
        bool ix = m && (id != 0.0f);
        idxk[j] = ix;

        float rx = a4[j].y - px, ry = a4[j].z - py;
        float s  = rx * rx + ry * ry;
        float ir = rsqrtf(s);
        float rn = s * ir;
        rnv[j] = rn;
        dxv[j] = rx * ir;
        dyv[j] = ry * ir;

        float vdx = a4[j].w * 0.02f, vdy = vny[j] * 0.02f;
        float tx = rx + vdx, ty = ry + vdy;
        float bb = rn + tx * tx + ty * ty - (vdx * vdx + vdy * vdy);
        bb = ix ? bb : 1.0f;
        bv[j] = __fsqrt_rn(fmaxf(bb, 1e-12f)) * 0.5f;
    }

    // ============ mono nets on own 4 ============
    float att4[4], rep4[4], del4[4];
    mono_batch<4>(sT[1], sN[1], sB[1], rnv, att4);
    mono_batch<4>(sT[0], sN[0], sB[0], bv,  rep4);

    bool same = (countl[0] == countl[1]) & (countl[0] == countl[2]) &
                (countl[0] == countl[3]);
    float oc0 = __shfl_xor_sync(amask, countl[0], 1);
    same = same && (countl[0] == oc0);
    if (__all_sync(amask, same)) {
        float du = mono1(sT[3], sN[3], sB[3], countl[0]);
#pragma unroll
        for (int j = 0; j < 4; j++) del4[j] = du;
    } else {
        mono_batch<4>(sT[3], sN[3], sB[3], countl, del4);
    }

    float v2   = vx * vx + vy * vy;
    float ang2 = sS[2];

    // ============ neighbor forces (own 4), angle-clamped, then pair-reduce ==
    float fnx = 0.0f, fny = 0.0f;
#pragma unroll
    for (int j = 0; j < 4; j++) {
        bool ix = idxk[j];
        float da  = del4[j] * att4[j];
        float fax = ix ? da * dxv[j] : 0.0f;
        float fay = ix ? da * dyv[j] : 0.0f;
        float frx = ix ? rep4[j] * dxv[j] : 0.0f;
        float fry = ix ? rep4[j] * dyv[j] : 0.0f;

        float num = vx * fax + vy * fay;
        float nn  = fax * fax + fay * fay;
        bool keep = num * num > ang2 * fmaxf(v2 * nn, 1e-16f);
        fnx += keep ? fax : 0.0f;
        fny += keep ? fay : 0.0f;

        num  = vx * frx + vy * fry;
        nn   = frx * frx + fry * fry;
        keep = num * num > ang2 * fmaxf(v2 * nn, 1e-16f);
        fnx += keep ? frx : 0.0f;
        fny += keep ? fry : 0.0f;
    }
    fnx += __shfl_xor_sync(amask, fnx, 1);
    fny += __shfl_xor_sync(amask, fny, 1);

    // ============ border force: this thread handles border term h ==========
    float bxc = e0.z;
    float rb  = bxc - sS[3 + h];
    float bm  = mono1(sT[2], sN[2], sB[2], fabsf(rb));
    float fv  = bm * copysignf(1.0f, rb);
    float fbyl = 0.0f;
    {
        float num = vy * fv, nn = fv * fv;
        if (num * num > ang2 * fmaxf(v2 * nn, 1e-16f)) fbyl = fv;
    }
    float fby = fbyl + __shfl_xor_sync(amask, fbyl, 1);

    // ============ destination force ============
    float speed = __fsqrt_rn(v2);
    float ip0 = sS[0], p1 = sS[1];
    float fdx = (p1 * speed - vx) * ip0;
    float fdy = (-vy) * ip0;
    {
        float num = vx * fdx + vy * fdy;
        float nn  = fdx * fdx + fdy * fdy;
        bool keep = num * num > ang2 * fmaxf(v2 * nn, 1e-16f);
        fdx = keep ? fdx : 0.0f;
        fdy = keep ? fdy : 0.0f;
    }

    // ============ output: (N, 3, 2); pair splits the 3 float2 stores =======
    float2* o = reinterpret_cast<float2*>(out) + (size_t)n * 3;
    if (h == 0) {
        o[0] = make_float2(fdx, fdy);
        o[1] = make_float2(fnx, fny);
    } else {
        o[2] = make_float2(0.0f, fby);
    }
}

extern "C" void kernel_launch(void* const* d_in, const int* in_sizes, int n_in,
                              void* d_out, int out_size)
{
    const float* ego    = (const float*)d_in[0];
    const float* nei    = (const float*)d_in[1];
    const float* border = (const float*)d_in[2];
    const float* rec    = (const float*)d_in[3];
    const float* p_dest = (const float*)d_in[4];
    const float* angle  = (const float*)d_in[5];

    sfm_preprocess<<<1, 32>>>(
        (const float*)d_in[6],  (const float*)d_in[7],  (const float*)d_in[8],  (const float*)d_in[9],
        (const float*)d_in[10], (const float*)d_in[11], (const float*)d_in[12], (const float*)d_in[13],
        (const float*)d_in[14], (const float*)d_in[15], (const float*)d_in[16], (const float*)d_in[17],
        (const float*)d_in[18], (const float*)d_in[19], (const float*)d_in[20], (const float*)d_in[21],
        p_dest, angle, border);

    int N = in_sizes[0] / 16;
    int blocks = (N + 127) / 128;   // 128 agents per block, 256 threads
    sfm_main<<<blocks, 256>>>(ego, nei, rec, (float*)d_out, N);
}

// round 9
// speedup vs baseline: 1.7188x; 1.0625x over previous
#include <cuda_runtime.h>

#define KNEI 8
#define EHID 16
// 256 threads per block = 128 agents per block, 2 threads per agent.

__device__ __forceinline__ float ex2f(float x) {
    float r; asm("ex2.approx.f32 %0, %1;" : "=f"(r) : "f"(x)); return r;
}
__device__ __forceinline__ float sqrt_apx(float x) {
    float r; asm("sqrt.approx.f32 %0, %1;" : "=f"(r) : "f"(x)); return r;
}

struct Net { float w[EHID]; float c[EHID]; float bias; int nnz; };
__device__ Net  g_nets[4];   // 0=rep, 1=att, 2=bor, 3=del
__device__ float g_scal[8];  // inv_p0, p1, ang^2, border[0], border[3]

// ---------------------------------------------------------------------------
// Fold each mono net  y = b2 + sum_i w2_i * exp(-(w1_i x + b1_i))
// into               y = bias + sum_{w1_i != 0} c_i * exp2(w'_i * x)
// ---------------------------------------------------------------------------
__global__ void sfm_preprocess(
    const float* __restrict__ rep_w1, const float* __restrict__ rep_b1,
    const float* __restrict__ rep_w2, const float* __restrict__ rep_b2,
    const float* __restrict__ att_w1, const float* __restrict__ att_b1,
    const float* __restrict__ att_w2, const float* __restrict__ att_b2,
    const float* __restrict__ bor_w1, const float* __restrict__ bor_b1,
    const float* __restrict__ bor_w2, const float* __restrict__ bor_b2,
    const float* __restrict__ del_w1, const float* __restrict__ del_b1,
    const float* __restrict__ del_w2, const float* __restrict__ del_b2,
    const float* __restrict__ p_dest, const float* __restrict__ angle,
    const float* __restrict__ border)
{
    int t = threadIdx.x;
    if (t < 4) {
        const float* w1 = (t==0)?rep_w1:(t==1)?att_w1:(t==2)?bor_w1:del_w1;
        const float* b1 = (t==0)?rep_b1:(t==1)?att_b1:(t==2)?bor_b1:del_b1;
        const float* w2 = (t==0)?rep_w2:(t==1)?att_w2:(t==2)?bor_w2:del_w2;
        const float* b2 = (t==0)?rep_b2:(t==1)?att_b2:(t==2)?bor_b2:del_b2;
        const float LOG2E = 1.4426950408889634f;
        float bias = b2[0];
        int m = 0;
        for (int i = 0; i < EHID; i++) {
            float ci = w2[i] * expf(-b1[i]);
            float wi = w1[i];
            if (wi != 0.0f) {
                g_nets[t].w[m] = -wi * LOG2E;
                g_nets[t].c[m] = ci;
                m++;
            } else {
                bias += ci;
            }
        }
        for (int i = m; i < EHID; i++) { g_nets[t].w[i] = 0.0f; g_nets[t].c[i] = 0.0f; }
        g_nets[t].bias = bias;
        g_nets[t].nnz  = m;
    } else if (t == 4) {
        g_scal[0] = 1.0f / p_dest[0];
        g_scal[1] = p_dest[1];
        float a = angle[0];
        g_scal[2] = a * a;
        g_scal[3] = border[0];
        g_scal[4] = border[3];
    }
}

template <int NB>
__device__ __forceinline__ void mono_batch(const float2* __restrict__ terms,
                                           int nn, float bias,
                                           const float* __restrict__ x,
                                           float* __restrict__ y)
{
#pragma unroll
    for (int k = 0; k < NB; k++) y[k] = bias;
    for (int t = 0; t < nn; t++) {
        float2 wc = terms[t];
#pragma unroll
        for (int k = 0; k < NB; k++)
            y[k] = fmaf(wc.y, ex2f(wc.x * x[k]), y[k]);
    }
}

__device__ __forceinline__ float mono1(const float2* __restrict__ terms,
                                       int nn, float bias, float x)
{
    float y = bias;
    for (int t = 0; t < nn; t++) {
        float2 wc = terms[t];
        y = fmaf(wc.y, ex2f(wc.x * x), y);
    }
    return y;
}

__global__ void __launch_bounds__(256, 4)
sfm_main(const float* __restrict__ ego, const float* __restrict__ nei,
         const float* __restrict__ rec, float* __restrict__ out, int N)
{
    __shared__ float2 sT[4][EHID];
    __shared__ float  sB[4];
    __shared__ int    sN[4];
    __shared__ float  sS[8];

    int t = threadIdx.x;
    if (t < 64) {
        int q = t >> 4, i = t & 15;
        sT[q][i] = make_float2(g_nets[q].w[i], g_nets[q].c[i]);
    } else if (t < 68) {
        sB[t - 64] = g_nets[t - 64].bias;
        sN[t - 64] = g_nets[t - 64].nnz;
    } else if (t < 73) {
        sS[t - 68] = g_scal[t - 68];
    }
    __syncthreads();

    int pid = t >> 1;          // pair (agent) index within block
    int h   = t & 1;           // half: this thread owns neighbor/buffer slots 4h..4h+3
    int n   = blockIdx.x * 128 + pid;
    if (n >= N) return;        // whole pairs exit together

    unsigned amask = __activemask();

    // ============ front-batched loads: own 4 nei rows + full ego + own rec half
    const float* nb = nei + (size_t)n * (KNEI * 16);
    float4 a4[4];
    float  vny[4];
#pragma unroll
    for (int j = 0; j < 4; j++)
        a4[j] = *reinterpret_cast<const float4*>(nb + (size_t)(4 * h + j) * 16);
#pragma unroll
    for (int j = 0; j < 4; j++)
        vny[j] = __ldg(nb + (size_t)(4 * h + j) * 16 + 4);   // same sector as a4[j]

    const float4* e4 = reinterpret_cast<const float4*>(ego) + (size_t)n * 4;
    float4 e0 = e4[0], e1 = e4[1], e2 = e4[2], e3 = e4[3];

    const float4* r4 = reinterpret_cast<const float4*>(rec) + (size_t)n * 4;
    float4 rr0 = r4[2 * h], rr1 = r4[2 * h + 1];

    // ============ unpack ego ============
    float px = e0.y, py = e0.z;
    float vx = e0.w, vy = e1.x;
    float ids[8] = { e1.w, e2.x, e2.y, e2.z, e2.w, e3.x, e3.y, e3.z };

    // ============ exchange neighbor ids -> full global-order nid8 ============
    float nidl[4] = { a4[0].x, a4[1].x, a4[2].x, a4[3].x };
    float nid8[8];
#pragma unroll
    for (int j = 0; j < 4; j++) {
        float o = __shfl_xor_sync(amask, nidl[j], 1);
        nid8[j]     = h ? o       : nidl[j];   // global slots 0..3
        nid8[4 + j] = h ? nidl[j] : o;         // global slots 4..7
    }

    // ============ buffer membership on own 4 slots ============
    float bidl[4] = { rr0.x, rr0.z, rr1.x, rr1.z };
    float bctl[4] = { rr0.y, rr0.w, rr1.y, rr1.w };
    unsigned mown = 0;
#pragma unroll
    for (int i = 0; i < 4; i++) {
        bool f = false;
#pragma unroll
        for (int j = 0; j < 8; j++) f |= (bidl[i] == nid8[j]);
        mown |= (f ? 1u : 0u) << (4 * h + i);
    }
    unsigned m8 = mown | __shfl_xor_sync(amask, mown, 1);

    // ============ counts. Fast path: no buffer id matches any neighbor id ==
    // Then ifin == false everywhere, so sorted keys pick the "new" candidates
    // and the fill, whose count is exactly 1.0 for every slot.
    float countl[4];
    bool fast = __all_sync(amask, m8 == 0);
    if (fast) {
#pragma unroll
        for (int i = 0; i < 4; i++) countl[i] = 1.0f;
    } else {
        // general path: R5's exchange + stable rank-select
        float ct2l[4];
#pragma unroll
        for (int i = 0; i < 4; i++) {
            bool f = (mown >> (4 * h + i)) & 1u;
            ct2l[i] = bctl[i] + (f ? 1.0f : 0.0f);
        }
        float ct8[8];
#pragma unroll
        for (int i = 0; i < 4; i++) {
            float o = __shfl_xor_sync(amask, ct2l[i], 1);
            ct8[i]     = h ? o       : ct2l[i];
            ct8[4 + i] = h ? ct2l[i] : o;
        }
#pragma unroll
        for (int i = 0; i < 4; i++) {
            int gi = 4 * h + i;
            float ci = 1.0f;
            int seen = 0;
#pragma unroll
            for (int k = 0; k < 8; k++) {
                bool b = (m8 >> k) & 1u;
                bool take = b && (seen == gi);
                ci = take ? ct8[k] : ci;
                seen += b ? 1 : 0;
            }
            countl[i] = ci;
        }
    }

    // ============ geometry for own 4 neighbors ============
    bool  idxk[4];
    float rnv[4], bv[4], dxv[4], dyv[4];
#pragma unroll
    for (int j = 0; j < 4; j++) {
        float id = a4[j].x;
        bool m = false;
#pragma unroll
        for (int q = 0; q < 8; q++) m |= (id == ids[q]);
        bool ix = m && (id != 0.0f);
        idxk[j] = ix;

        float rx = a4[j].y - px, ry = a4[j].z - py;
        float s  = rx * rx + ry * ry;
        float ir = rsqrtf(s);
        float rn = s * ir;
        rnv[j] = rn;
        dxv[j] = rx * ir;
        dyv[j] = ry * ir;

        float vdx = a4[j].w * 0.02f, vdy = vny[j] * 0.02f;
        float tx = rx + vdx, ty = ry + vdy;
        float bb = rn + tx * tx + ty * ty - (vdx * vdx + vdy * vdy);
        bb = ix ? bb : 1.0f;
        bv[j] = sqrt_apx(fmaxf(bb, 1e-12f)) * 0.5f;
    }

    // ============ mono nets on own 4 ============
    float att4[4], rep4[4], del4[4];
    mono_batch<4>(sT[1], sN[1], sB[1], rnv, att4);
    mono_batch<4>(sT[0], sN[0], sB[0], bv,  rep4);

    if (fast) {
        float du = mono1(sT[3], sN[3], sB[3], 1.0f);
#pragma unroll
        for (int j = 0; j < 4; j++) del4[j] = du;
    } else {
        bool same = (countl[0] == countl[1]) & (countl[0] == countl[2]) &
                    (countl[0] == countl[3]);
        float oc0 = __shfl_xor_sync(amask, countl[0], 1);
        same = same && (countl[0] == oc0);
        if (__all_sync(amask, same)) {
            float du = mono1(sT[3], sN[3], sB[3], countl[0]);
#pragma unroll
            for (int j = 0; j < 4; j++) del4[j] = du;
        } else {
            mono_batch<4>(sT[3], sN[3], sB[3], countl, del4);
        }
    }

    float v2   = vx * vx + vy * vy;
    float ang2 = sS[2];

    // ============ neighbor forces (own 4), angle-clamped, then pair-reduce ==
    float fnx = 0.0f, fny = 0.0f;
#pragma unroll
    for (int j = 0; j < 4; j++) {
        bool ix = idxk[j];
        float da  = del4[j] * att4[j];
        float fax = ix ? da * dxv[j] : 0.0f;
        float fay = ix ? da * dyv[j] : 0.0f;
        float frx = ix ? rep4[j] * dxv[j] : 0.0f;
        float fry = ix ? rep4[j] * dyv[j] : 0.0f;

        float num = vx * fax + vy * fay;
        float nn  = fax * fax + fay * fay;
        bool keep = num * num > ang2 * fmaxf(v2 * nn, 1e-16f);
        fnx += keep ? fax : 0.0f;
        fny += keep ? fay : 0.0f;

        num  = vx * frx + vy * fry;
        nn   = frx * frx + fry * fry;
        keep = num * num > ang2 * fmaxf(v2 * nn, 1e-16f);
        fnx += keep ? frx : 0.0f;
        fny += keep ? fry : 0.0f;
    }
    fnx += __shfl_xor_sync(amask, fnx, 1);
    fny += __shfl_xor_sync(amask, fny, 1);

    // ============ border force: this thread handles border term h ==========
    float bxc = e0.z;
    float rb  = bxc - sS[3 + h];
    float bm  = mono1(sT[2], sN[2], sB[2], fabsf(rb));
    float fv  = bm * copysignf(1.0f, rb);
    float fbyl = 0.0f;
    {
        float num = vy * fv, nn = fv * fv;
        if (num * num > ang2 * fmaxf(v2 * nn, 1e-16f)) fbyl = fv;
    }
    float fby = fbyl + __shfl_xor_sync(amask, fbyl, 1);

    // ============ destination force ============
    float speed = sqrt_apx(v2);
    float ip0 = sS[0], p1 = sS[1];
    float fdx = (p1 * speed - vx) * ip0;
    float fdy = (-vy) * ip0;
    {
        float num = vx * fdx + vy * fdy;
        float nn  = fdx * fdx + fdy * fdy;
        bool keep = num * num > ang2 * fmaxf(v2 * nn, 1e-16f);
        fdx = keep ? fdx : 0.0f;
        fdy = keep ? fdy : 0.0f;
    }

    // ============ output: (N, 3, 2); pair splits the 3 float2 stores =======
    float2* o = reinterpret_cast<float2*>(out) + (size_t)n * 3;
    if (h == 0) {
        o[0] = make_float2(fdx, fdy);
        o[1] = make_float2(fnx, fny);
    } else {
        o[2] = make_float2(0.0f, fby);
    }
}

extern "C" void kernel_launch(void* const* d_in, const int* in_sizes, int n_in,
                              void* d_out, int out_size)
{
    const float* ego    = (const float*)d_in[0];
    const float* nei    = (const float*)d_in[1];
    const float* border = (const float*)d_in[2];
    const float* rec    = (const float*)d_in[3];
    const float* p_dest = (const float*)d_in[4];
    const float* angle  = (const float*)d_in[5];

    sfm_preprocess<<<1, 32>>>(
        (const float*)d_in[6],  (const float*)d_in[7],  (const float*)d_in[8],  (const float*)d_in[9],
        (const float*)d_in[10], (const float*)d_in[11], (const float*)d_in[12], (const float*)d_in[13],
        (const float*)d_in[14], (const float*)d_in[15], (const float*)d_in[16], (const float*)d_in[17],
        (const float*)d_in[18], (const float*)d_in[19], (const float*)d_in[20], (const float*)d_in[21],
        p_dest, angle, border);

    int N = in_sizes[0] / 16;
    int blocks = (N + 127) / 128;   // 128 agents per block, 256 threads
    sfm_main<<<blocks, 256>>>(ego, nei, rec, (float*)d_out, N);
}

// round 10
// speedup vs baseline: 1.7872x; 1.0398x over previous
#include <cuda_runtime.h>

#define KNEI 8
#define EHID 16
// 256 threads per block = 128 agents per block, 2 threads per agent.
// Thread h of a pair owns neighbor slots {h, h+2, h+4, h+6} (row-interleaved
// so a lane pair's loads land in the SAME 128B line) and buffer slots
// {4h..4h+3} (contiguous, already line-coalesced).

__device__ __forceinline__ float ex2f(float x) {
    float r; asm("ex2.approx.f32 %0, %1;" : "=f"(r) : "f"(x)); return r;
}
__device__ __forceinline__ float sqrt_apx(float x) {
    float r; asm("sqrt.approx.f32 %0, %1;" : "=f"(r) : "f"(x)); return r;
}

struct Net { float w[EHID]; float c[EHID]; float bias; int nnz; };
__device__ Net  g_nets[4];   // 0=rep, 1=att, 2=bor, 3=del
__device__ float g_scal[8];  // inv_p0, p1, ang^2, border[0], border[3]

// ---------------------------------------------------------------------------
// Fold each mono net  y = b2 + sum_i w2_i * exp(-(w1_i x + b1_i))
// into               y = bias + sum_{w1_i != 0} c_i * exp2(w'_i * x)
// ---------------------------------------------------------------------------
__global__ void sfm_preprocess(
    const float* __restrict__ rep_w1, const float* __restrict__ rep_b1,
    const float* __restrict__ rep_w2, const float* __restrict__ rep_b2,
    const float* __restrict__ att_w1, const float* __restrict__ att_b1,
    const float* __restrict__ att_w2, const float* __restrict__ att_b2,
    const float* __restrict__ bor_w1, const float* __restrict__ bor_b1,
    const float* __restrict__ bor_w2, const float* __restrict__ bor_b2,
    const float* __restrict__ del_w1, const float* __restrict__ del_b1,
    const float* __restrict__ del_w2, const float* __restrict__ del_b2,
    const float* __restrict__ p_dest, const float* __restrict__ angle,
    const float* __restrict__ border)
{
    int t = threadIdx.x;
    if (t < 4) {
        const float* w1 = (t==0)?rep_w1:(t==1)?att_w1:(t==2)?bor_w1:del_w1;
        const float* b1 = (t==0)?rep_b1:(t==1)?att_b1:(t==2)?bor_b1:del_b1;
        const float* w2 = (t==0)?rep_w2:(t==1)?att_w2:(t==2)?bor_w2:del_w2;
        const float* b2 = (t==0)?rep_b2:(t==1)?att_b2:(t==2)?bor_b2:del_b2;
        const float LOG2E = 1.4426950408889634f;
        float bias = b2[0];
        int m = 0;
        for (int i = 0; i < EHID; i++) {
            float ci = w2[i] * expf(-b1[i]);
            float wi = w1[i];
            if (wi != 0.0f) {
                g_nets[t].w[m] = -wi * LOG2E;
                g_nets[t].c[m] = ci;
                m++;
            } else {
                bias += ci;
            }
        }
        for (int i = m; i < EHID; i++) { g_nets[t].w[i] = 0.0f; g_nets[t].c[i] = 0.0f; }
        g_nets[t].bias = bias;
        g_nets[t].nnz  = m;
    } else if (t == 4) {
        g_scal[0] = 1.0f / p_dest[0];
        g_scal[1] = p_dest[1];
        float a = angle[0];
        g_scal[2] = a * a;
        g_scal[3] = border[0];
        g_scal[4] = border[3];
    }
}

template <int NB>
__device__ __forceinline__ void mono_batch(const float2* __restrict__ terms,
                                           int nn, float bias,
                                           const float* __restrict__ x,
                                           float* __restrict__ y)
{
#pragma unroll
    for (int k = 0; k < NB; k++) y[k] = bias;
    for (int t = 0; t < nn; t++) {
        float2 wc = terms[t];
#pragma unroll
        for (int k = 0; k < NB; k++)
            y[k] = fmaf(wc.y, ex2f(wc.x * x[k]), y[k]);
    }
}

__device__ __forceinline__ float mono1(const float2* __restrict__ terms,
                                       int nn, float bias, float x)
{
    float y = bias;
    for (int t = 0; t < nn; t++) {
        float2 wc = terms[t];
        y = fmaf(wc.y, ex2f(wc.x * x), y);
    }
    return y;
}

__global__ void __launch_bounds__(256, 4)
sfm_main(const float* __restrict__ ego, const float* __restrict__ nei,
         const float* __restrict__ rec, float* __restrict__ out, int N)
{
    __shared__ float2 sT[4][EHID];
    __shared__ float  sB[4];
    __shared__ int    sN[4];
    __shared__ float  sS[8];

    int t = threadIdx.x;
    if (t < 64) {
        int q = t >> 4, i = t & 15;
        sT[q][i] = make_float2(g_nets[q].w[i], g_nets[q].c[i]);
    } else if (t < 68) {
        sB[t - 64] = g_nets[t - 64].bias;
        sN[t - 64] = g_nets[t - 64].nnz;
    } else if (t < 73) {
        sS[t - 68] = g_scal[t - 68];
    }
    __syncthreads();

    int pid = t >> 1;          // pair (agent) index within block
    int h   = t & 1;           // lane-in-pair
    int n   = blockIdx.x * 128 + pid;
    if (n >= N) return;        // whole pairs exit together

    unsigned amask = __activemask();

    // ============ front-batched loads ============
    // Own neighbor slots g = 2j + h  (lane pair -> rows 2j, 2j+1 -> SAME
    // 128B line -> nei LDGs coalesce to 16 lines/warp instead of 32).
    const float* nb = nei + (size_t)n * (KNEI * 16);
    float4 a4[4];
    float  vny[4];
#pragma unroll
    for (int j = 0; j < 4; j++)
        a4[j] = *reinterpret_cast<const float4*>(nb + (size_t)(2 * j + h) * 16);
#pragma unroll
    for (int j = 0; j < 4; j++)
        vny[j] = __ldg(nb + (size_t)(2 * j + h) * 16 + 4);   // same sector as a4[j]

    const float4* e4 = reinterpret_cast<const float4*>(ego) + (size_t)n * 4;
    float4 e0 = e4[0], e1 = e4[1], e2 = e4[2], e3 = e4[3];

    // Own buffer slots 4h..4h+3 (contiguous halves; already line-coalesced)
    const float4* r4 = reinterpret_cast<const float4*>(rec) + (size_t)n * 4;
    float4 rr0 = r4[2 * h], rr1 = r4[2 * h + 1];

    // ============ unpack ego ============
    float px = e0.y, py = e0.z;
    float vx = e0.w, vy = e1.x;
    float ids[8] = { e1.w, e2.x, e2.y, e2.z, e2.w, e3.x, e3.y, e3.z };

    // ============ exchange neighbor ids -> global-order nid8 ============
    // own j-th id is global slot 2j+h; partner's is 2j+(1-h).
    float nidl[4] = { a4[0].x, a4[1].x, a4[2].x, a4[3].x };
    float nid8[8];
#pragma unroll
    for (int j = 0; j < 4; j++) {
        float o = __shfl_xor_sync(amask, nidl[j], 1);
        nid8[2 * j]     = h ? o       : nidl[j];
        nid8[2 * j + 1] = h ? nidl[j] : o;
    }

    // ============ buffer membership on own 4 buffer slots ============
    float bidl[4] = { rr0.x, rr0.z, rr1.x, rr1.z };
    float bctl[4] = { rr0.y, rr0.w, rr1.y, rr1.w };
    unsigned mown = 0;
#pragma unroll
    for (int i = 0; i < 4; i++) {
        bool f = false;
#pragma unroll
        for (int j = 0; j < 8; j++) f |= (bidl[i] == nid8[j]);
        mown |= (f ? 1u : 0u) << (4 * h + i);
    }
    unsigned m8 = mown | __shfl_xor_sync(amask, mown, 1);

    // ============ counts for own neighbor slots gi = 2i+h ============
    // Fast path: no buffer id matches any neighbor id -> every count is 1.0
    float countl[4];
    bool fast = __all_sync(amask, m8 == 0);
    if (fast) {
#pragma unroll
        for (int i = 0; i < 4; i++) countl[i] = 1.0f;
    } else {
        // general path: exchange ct2 (buffer order) + stable rank-select
        float ct2l[4];
#pragma unroll
        for (int i = 0; i < 4; i++) {
            bool f = (mown >> (4 * h + i)) & 1u;
            ct2l[i] = bctl[i] + (f ? 1.0f : 0.0f);
        }
        float ct8[8];
#pragma unroll
        for (int i = 0; i < 4; i++) {
            float o = __shfl_xor_sync(amask, ct2l[i], 1);
            ct8[i]     = h ? o       : ct2l[i];
            ct8[4 + i] = h ? ct2l[i] : o;
        }
#pragma unroll
        for (int i = 0; i < 4; i++) {
            int gi = 2 * i + h;
            float ci = 1.0f;
            int seen = 0;
#pragma unroll
            for (int k = 0; k < 8; k++) {
                bool b = (m8 >> k) & 1u;
                bool take = b && (seen == gi);
                ci = take ? ct8[k] : ci;
                seen += b ? 1 : 0;
            }
            countl[i] = ci;
        }
    }

    // ============ geometry for own 4 neighbors ============
    bool  idxk[4];
    float rnv[4], bv[4], dxv[4], dyv[4];
#pragma unroll
    for (int j = 0; j < 4; j++) {
        float id = a4[j].x;
        bool m = false;
#pragma unroll
        for (int q = 0; q < 8; q++) m |= (id == ids[q]);
        bool ix = m && (id != 0.0f);
        idxk[j] = ix;

        float rx = a4[j].y - px, ry = a4[j].z - py;
        float s  = rx * rx + ry * ry;
        float ir = rsqrtf(s);
        float rn = s * ir;
        rnv[j] = rn;
        dxv[j] = rx * ir;
        dyv[j] = ry * ir;

        float vdx = a4[j].w * 0.02f, vdy = vny[j] * 0.02f;
        float tx = rx + vdx, ty = ry + vdy;
        float bb = rn + tx * tx + ty * ty - (vdx * vdx + vdy * vdy);
        bb = ix ? bb : 1.0f;
        bv[j] = sqrt_apx(fmaxf(bb, 1e-12f)) * 0.5f;
    }

    // ============ mono nets on own 4 ============
    float att4[4], rep4[4], del4[4];
    mono_batch<4>(sT[1], sN[1], sB[1], rnv, att4);
    mono_batch<4>(sT[0], sN[0], sB[0], bv,  rep4);

    if (fast) {
        float du = mono1(sT[3], sN[3], sB[3], 1.0f);
#pragma unroll
        for (int j = 0; j < 4; j++) del4[j] = du;
    } else {
        bool same = (countl[0] == countl[1]) & (countl[0] == countl[2]) &
                    (countl[0] == countl[3]);
        float oc0 = __shfl_xor_sync(amask, countl[0], 1);
        same = same && (countl[0] == oc0);
        if (__all_sync(amask, same)) {
            float du = mono1(sT[3], sN[3], sB[3], countl[0]);
#pragma unroll
            for (int j = 0; j < 4; j++) del4[j] = du;
        } else {
            mono_batch<4>(sT[3], sN[3], sB[3], countl, del4);
        }
    }

    float v2   = vx * vx + vy * vy;
    float ang2 = sS[2];

    // ============ neighbor forces (own 4), angle-clamped, then pair-reduce ==
    float fnx = 0.0f, fny = 0.0f;
#pragma unroll
    for (int j = 0; j < 4; j++) {
        bool ix = idxk[j];
        float da  = del4[j] * att4[j];
        float fax = ix ? da * dxv[j] : 0.0f;
        float fay = ix ? da * dyv[j] : 0.0f;
        float frx = ix ? rep4[j] * dxv[j] : 0.0f;
        float fry = ix ? rep4[j] * dyv[j] : 0.0f;

        float num = vx * fax + vy * fay;
        float nn  = fax * fax + fay * fay;
        bool keep = num * num > ang2 * fmaxf(v2 * nn, 1e-16f);
        fnx += keep ? fax : 0.0f;
        fny += keep ? fay : 0.0f;

        num  = vx * frx + vy * fry;
        nn   = frx * frx + fry * fry;
        keep = num * num > ang2 * fmaxf(v2 * nn, 1e-16f);
        fnx += keep ? frx : 0.0f;
        fny += keep ? fry : 0.0f;
    }
    fnx += __shfl_xor_sync(amask, fnx, 1);
    fny += __shfl_xor_sync(amask, fny, 1);

    // ============ border force: this thread handles border term h ==========
    float bxc = e0.z;
    float rb  = bxc - sS[3 + h];
    float bm  = mono1(sT[2], sN[2], sB[2], fabsf(rb));
    float fv  = bm * copysignf(1.0f, rb);
    float fbyl = 0.0f;
    {
        float num = vy * fv, nn = fv * fv;
        if (num * num > ang2 * fmaxf(v2 * nn, 1e-16f)) fbyl = fv;
    }
    float fby = fbyl + __shfl_xor_sync(amask, fbyl, 1);

    // ============ destination force ============
    float speed = sqrt_apx(v2);
    float ip0 = sS[0], p1 = sS[1];
    float fdx = (p1 * speed - vx) * ip0;
    float fdy = (-vy) * ip0;
    {
        float num = vx * fdx + vy * fdy;
        float nn  = fdx * fdx + fdy * fdy;
        bool keep = num * num > ang2 * fmaxf(v2 * nn, 1e-16f);
        fdx = keep ? fdx : 0.0f;
        fdy = keep ? fdy : 0.0f;
    }

    // ============ output: (N, 3, 2); pair splits the 3 float2 stores =======
    float2* o = reinterpret_cast<float2*>(out) + (size_t)n * 3;
    if (h == 0) {
        o[0] = make_float2(fdx, fdy);
        o[1] = make_float2(fnx, fny);
    } else {
        o[2] = make_float2(0.0f, fby);
    }
}

extern "C" void kernel_launch(void* const* d_in, const int* in_sizes, int n_in,
                              void* d_out, int out_size)
{
    const float* ego    = (const float*)d_in[0];
    const float* nei    = (const float*)d_in[1];
    const float* border = (const float*)d_in[2];
    const float* rec    = (const float*)d_in[3];
    const float* p_dest = (const float*)d_in[4];
    const float* angle  = (const float*)d_in[5];

    sfm_preprocess<<<1, 32>>>(
        (const float*)d_in[6],  (const float*)d_in[7],  (const float*)d_in[8],  (const float*)d_in[9],
        (const float*)d_in[10], (const float*)d_in[11], (const float*)d_in[12], (const float*)d_in[13],
        (const float*)d_in[14], (const float*)d_in[15], (const float*)d_in[16], (const float*)d_in[17],
        (const float*)d_in[18], (const float*)d_in[19], (const float*)d_in[20], (const float*)d_in[21],
        p_dest, angle, border);

    int N = in_sizes[0] / 16;
    int blocks = (N + 127) / 128;   // 128 agents per block, 256 threads
    sfm_main<<<blocks, 256>>>(ego, nei, rec, (float*)d_out, N);
}